// round 4
// baseline (speedup 1.0000x reference)
#include <cuda_runtime.h>
#include <math.h>

#define EPS 1e-8f

// One warp processes 8 rows; 4 lanes per row; each lane owns 16 contiguous
// columns (4 x float4). Default-cached loads (R3 showed .cg regresses).
// Quantum cos-product is computed BEFORE the reduction so all 32 load
// registers die early -> lower live range -> higher occupancy.
__global__ void __launch_bounds__(256) hybrid_rbf_kernel(
    const float* __restrict__ x,
    const float* __restrict__ y,
    float* __restrict__ out,
    int B)
{
    const int warp_id = (blockIdx.x * blockDim.x + threadIdx.x) >> 5;
    const int lane    = threadIdx.x & 31;
    const int group   = lane >> 2;   // 0..7 : which row within the warp
    const int j       = lane & 3;    // 0..3 : 16-column slice within the row
    const int row     = warp_id * 8 + group;
    if (row >= B) return;

    const float4* __restrict__ xr = reinterpret_cast<const float4*>(x + (size_t)row * 64) + j * 4;
    const float4* __restrict__ yr = reinterpret_cast<const float4*>(y + (size_t)row * 64) + j * 4;

    // Issue all loads up front (MLP = 8)
    const float4 xv0 = xr[0], xv1 = xr[1], xv2 = xr[2], xv3 = xr[3];
    const float4 yv0 = yr[0], yv1 = yr[1], yv2 = yr[2], yv3 = yr[3];

    // Fused single-pass moments: Sx, Sxx, Sy, Syy, Sxy — straight off the vectors
    float sx  = xv0.x + xv0.y + xv0.z + xv0.w
              + xv1.x + xv1.y + xv1.z + xv1.w
              + xv2.x + xv2.y + xv2.z + xv2.w
              + xv3.x + xv3.y + xv3.z + xv3.w;
    float sy  = yv0.x + yv0.y + yv0.z + yv0.w
              + yv1.x + yv1.y + yv1.z + yv1.w
              + yv2.x + yv2.y + yv2.z + yv2.w
              + yv3.x + yv3.y + yv3.z + yv3.w;

    float sxx = 0.f, syy = 0.f, sxy = 0.f;
    {
        #define ACC(xv, yv)                       \
            sxx = fmaf((xv), (xv), sxx);          \
            syy = fmaf((yv), (yv), syy);          \
            sxy = fmaf((xv), (yv), sxy);
        ACC(xv0.x, yv0.x) ACC(xv0.y, yv0.y) ACC(xv0.z, yv0.z) ACC(xv0.w, yv0.w)
        ACC(xv1.x, yv1.x) ACC(xv1.y, yv1.y) ACC(xv1.z, yv1.z) ACC(xv1.w, yv1.w)
        ACC(xv2.x, yv2.x) ACC(xv2.y, yv2.y) ACC(xv2.z, yv2.z) ACC(xv2.w, yv2.w)
        ACC(xv3.x, yv3.x) ACC(xv3.y, yv3.y) ACC(xv3.z, yv3.z) ACC(xv3.w, yv3.w)
        #undef ACC
    }

    // Quantum term computed NOW so xv*/yv* registers die before the reduction.
    // Only j==0 lanes hold raw cols 0..7; other lanes compute garbage into q
    // (harmless, discarded).
    float q = __cosf(xv0.x - yv0.x) * __cosf(xv0.y - yv0.y)
            * __cosf(xv0.z - yv0.z) * __cosf(xv0.w - yv0.w)
            * __cosf(xv1.x - yv1.x) * __cosf(xv1.y - yv1.y)
            * __cosf(xv1.z - yv1.z) * __cosf(xv1.w - yv1.w);

    // Segmented butterfly reduction over the aligned 4-lane group
    #pragma unroll
    for (int o = 1; o <= 2; o <<= 1) {
        sx  += __shfl_xor_sync(0xFFFFFFFFu, sx,  o);
        sy  += __shfl_xor_sync(0xFFFFFFFFu, sy,  o);
        sxx += __shfl_xor_sync(0xFFFFFFFFu, sxx, o);
        syy += __shfl_xor_sync(0xFFFFFFFFu, syy, o);
        sxy += __shfl_xor_sync(0xFFFFFFFFu, sxy, o);
    }

    if (j == 0) {
        const float inv_n   = 1.0f / 64.0f;
        const float inv_nm1 = 1.0f / 63.0f;
        const float mx = sx * inv_n;
        const float my = sy * inv_n;
        const float vx = fmaxf((sxx - 64.0f * mx * mx) * inv_nm1, 0.0f);
        const float vy = fmaxf((syy - 64.0f * my * my) * inv_nm1, 0.0f);
        const float fx = 1.0f / (sqrtf(vx) + EPS);
        const float fy = 1.0f / (sqrtf(vy) + EPS);
        const float cov = sxy - 64.0f * mx * my;     // sum (x-mx)(y-my)
        // sum (xhat - yhat)^2 = 63*vx*fx^2 + 63*vy*fy^2 - 2*cov*fx*fy
        const float ss = 63.0f * vx * fx * fx
                       + 63.0f * vy * fy * fy
                       - 2.0f * cov * fx * fy;

        out[row] = __expf(-ss) + q * q;
    }
}

extern "C" void kernel_launch(void* const* d_in, const int* in_sizes, int n_in,
                              void* d_out, int out_size)
{
    const float* x = (const float*)d_in[0];
    const float* y = (const float*)d_in[1];
    float* out = (float*)d_out;
    const int B = in_sizes[0] / 64;

    const int threads = 256;                    // 8 warps -> 64 rows per block
    const int rows_per_block = (threads / 32) * 8;
    const int blocks = (B + rows_per_block - 1) / rows_per_block;
    hybrid_rbf_kernel<<<blocks, threads>>>(x, y, out, B);
}

// round 5
// speedup vs baseline: 1.0800x; 1.0800x over previous
#include <cuda_runtime.h>
#include <math.h>

#define EPS 1e-8f

// R2 structure (best: 81.0us, DRAM 83.7%). One warp = 8 rows; 4 lanes per row;
// each lane owns 16 contiguous columns (4 x float4). Default-cached loads
// (.cg regressed in R3). Quantum cos-product predicated to j==0 (all-lane MUFU
// regressed in R4) but hoisted before the shuffle chain for early reg death.
__global__ void __launch_bounds__(256) hybrid_rbf_kernel(
    const float* __restrict__ x,
    const float* __restrict__ y,
    float* __restrict__ out,
    int B)
{
    const int warp_id = (blockIdx.x * blockDim.x + threadIdx.x) >> 5;
    const int lane    = threadIdx.x & 31;
    const int group   = lane >> 2;   // 0..7 : which row within the warp
    const int j       = lane & 3;    // 0..3 : 16-column slice within the row
    const int row     = warp_id * 8 + group;
    if (row >= B) return;

    const float4* __restrict__ xr = reinterpret_cast<const float4*>(x + (size_t)row * 64) + j * 4;
    const float4* __restrict__ yr = reinterpret_cast<const float4*>(y + (size_t)row * 64) + j * 4;

    // Issue all loads up front (MLP = 8)
    float4 xv0 = xr[0], xv1 = xr[1], xv2 = xr[2], xv3 = xr[3];
    float4 yv0 = yr[0], yv1 = yr[1], yv2 = yr[2], yv3 = yr[3];

    // Fused single-pass moments: Sx, Sxx, Sy, Syy, Sxy
    float sx = 0.f, sxx = 0.f, sy = 0.f, syy = 0.f, sxy = 0.f;
    {
        const float4 xs[4] = {xv0, xv1, xv2, xv3};
        const float4 ys[4] = {yv0, yv1, yv2, yv3};
        #pragma unroll
        for (int k = 0; k < 4; k++) {
            const float xa[4] = {xs[k].x, xs[k].y, xs[k].z, xs[k].w};
            const float ya[4] = {ys[k].x, ys[k].y, ys[k].z, ys[k].w};
            #pragma unroll
            for (int e = 0; e < 4; e++) {
                const float xv = xa[e], yv = ya[e];
                sx  += xv;
                sy  += yv;
                sxx = fmaf(xv, xv, sxx);
                syy = fmaf(yv, yv, syy);
                sxy = fmaf(xv, yv, sxy);
            }
        }
    }

    // Quantum term (predicated: only the 8 j==0 lanes run the MUFUs, as in R2),
    // hoisted before the shuffles so xv*/yv* can retire during the reduction.
    float q = 0.f;
    if (j == 0) {
        q = __cosf(xv0.x - yv0.x) * __cosf(xv0.y - yv0.y)
          * __cosf(xv0.z - yv0.z) * __cosf(xv0.w - yv0.w)
          * __cosf(xv1.x - yv1.x) * __cosf(xv1.y - yv1.y)
          * __cosf(xv1.z - yv1.z) * __cosf(xv1.w - yv1.w);
    }

    // Segmented butterfly reduction over the aligned 4-lane group
    #pragma unroll
    for (int o = 1; o <= 2; o <<= 1) {
        sx  += __shfl_xor_sync(0xFFFFFFFFu, sx,  o);
        sy  += __shfl_xor_sync(0xFFFFFFFFu, sy,  o);
        sxx += __shfl_xor_sync(0xFFFFFFFFu, sxx, o);
        syy += __shfl_xor_sync(0xFFFFFFFFu, syy, o);
        sxy += __shfl_xor_sync(0xFFFFFFFFu, sxy, o);
    }

    if (j == 0) {
        const float inv_n   = 1.0f / 64.0f;
        const float inv_nm1 = 1.0f / 63.0f;
        const float mx = sx * inv_n;
        const float my = sy * inv_n;
        const float vx = fmaxf((sxx - 64.0f * mx * mx) * inv_nm1, 0.0f);
        const float vy = fmaxf((syy - 64.0f * my * my) * inv_nm1, 0.0f);
        const float fx = 1.0f / (sqrtf(vx) + EPS);
        const float fy = 1.0f / (sqrtf(vy) + EPS);
        const float cov = sxy - 64.0f * mx * my;     // sum (x-mx)(y-my)
        // sum (xhat - yhat)^2 = 63*vx*fx^2 + 63*vy*fy^2 - 2*cov*fx*fy
        const float ss = 63.0f * vx * fx * fx
                       + 63.0f * vy * fy * fy
                       - 2.0f * cov * fx * fy;

        out[row] = __expf(-ss) + q * q;
    }
}

extern "C" void kernel_launch(void* const* d_in, const int* in_sizes, int n_in,
                              void* d_out, int out_size)
{
    const float* x = (const float*)d_in[0];
    const float* y = (const float*)d_in[1];
    float* out = (float*)d_out;
    const int B = in_sizes[0] / 64;

    const int threads = 256;                    // 8 warps -> 64 rows per block
    const int rows_per_block = (threads / 32) * 8;
    const int blocks = (B + rows_per_block - 1) / rows_per_block;
    hybrid_rbf_kernel<<<blocks, threads>>>(x, y, out, B);
}